// round 7
// baseline (speedup 1.0000x reference)
#include <cuda_runtime.h>
#include <math.h>
#include <stdint.h>

// Problem constants (fixed by the dataset)
#define N_NODES 100000
#define FEAT    256
#define RANK    64
#define HID     512
#define OUTD    128
#define E_EDGES 200000
#define KORD    4
#define DEG     8

// num = DEG^(1/K) = 8^0.25
#define NUMV 1.6817928305074290860f
// C1 = num / (K-1)! = num / 6
#define C1V  (NUMV / 6.0f)

// -------- scratch (device globals: the sanctioned no-alloc workaround) -----
__device__ float g_emb1[(size_t)N_NODES * RANK];   // num*(emb@Wp + bp)   25.6 MB
__device__ float g_h   [(size_t)N_NODES * HID];    // relu(emb@W1 + b1)  204.8 MB
__device__ float g_emb2[(size_t)N_NODES * OUTD];   // h@W2 + b2          51.2 MB

// ---------------------------------------------------------------------------
// Generic register-blocked SGEMM: C[M,N] = epi(A[M,K] @ B[K,N] + bias)
// EPI: 0 = none, 1 = relu, 2 = scale by alpha after bias
// Requires: K % BK == 0, N % BN == 0 (true for all three calls). M guarded.
// ---------------------------------------------------------------------------
template <int BM, int BN, int BK, int TM, int TN, int EPI>
__global__ __launch_bounds__(256) void sgemm_kernel(
    int M, int N, int K,
    const float* __restrict__ A, const float* __restrict__ B,
    const float* __restrict__ bias, float* __restrict__ C, float alpha)
{
    static_assert((BM / TM) * (BN / TN) == 256, "256 threads");
    __shared__ float As[BK][BM];   // A tile stored transposed
    __shared__ float Bs[BK][BN];

    const int tid     = threadIdx.x;
    const int tcols   = BN / TN;
    const int tr      = tid / tcols;
    const int tc      = tid % tcols;
    const int rowBase = blockIdx.y * BM;
    const int colBase = blockIdx.x * BN;

    const int aRow0 = tid / (BK / 4);
    const int aCol  = (tid % (BK / 4)) * 4;
    constexpr int ASTRIDE = 256 / (BK / 4);
    const int bRow0 = tid / (BN / 4);
    const int bCol  = (tid % (BN / 4)) * 4;
    constexpr int BSTRIDE = 256 / (BN / 4);

    float acc[TM][TN];
#pragma unroll
    for (int i = 0; i < TM; i++)
#pragma unroll
        for (int j = 0; j < TN; j++) acc[i][j] = 0.0f;

    for (int k0 = 0; k0 < K; k0 += BK) {
        // Load A tile (transposed into SMEM), guard rows beyond M
#pragma unroll
        for (int r = 0; r < BM; r += ASTRIDE) {
            const int row  = r + aRow0;
            const int grow = rowBase + row;
            float4 v = make_float4(0.f, 0.f, 0.f, 0.f);
            if (grow < M)
                v = *(const float4*)&A[(size_t)grow * K + k0 + aCol];
            As[aCol + 0][row] = v.x;
            As[aCol + 1][row] = v.y;
            As[aCol + 2][row] = v.z;
            As[aCol + 3][row] = v.w;
        }
        // Load B tile
#pragma unroll
        for (int r = 0; r < BK; r += BSTRIDE) {
            const int row = r + bRow0;
            *(float4*)&Bs[row][bCol] =
                *(const float4*)&B[(size_t)(k0 + row) * N + colBase + bCol];
        }
        __syncthreads();

#pragma unroll
        for (int kk = 0; kk < BK; kk++) {
            float ra[TM], rb[TN];
#pragma unroll
            for (int i = 0; i < TM; i += 4)
                *(float4*)&ra[i] = *(const float4*)&As[kk][tr * TM + i];
#pragma unroll
            for (int j = 0; j < TN; j += 4)
                *(float4*)&rb[j] = *(const float4*)&Bs[kk][tc * TN + j];
#pragma unroll
            for (int i = 0; i < TM; i++)
#pragma unroll
                for (int j = 0; j < TN; j++)
                    acc[i][j] += ra[i] * rb[j];
        }
        __syncthreads();
    }

    // Epilogue
#pragma unroll
    for (int i = 0; i < TM; i++) {
        const int grow = rowBase + tr * TM + i;
        if (grow >= M) continue;
#pragma unroll
        for (int j = 0; j < TN; j += 4) {
            const int gcol = colBase + tc * TN + j;
            const float4 bv = *(const float4*)&bias[gcol];
            float4 o;
            o.x = acc[i][j + 0] + bv.x;
            o.y = acc[i][j + 1] + bv.y;
            o.z = acc[i][j + 2] + bv.z;
            o.w = acc[i][j + 3] + bv.w;
            if (EPI == 1) {
                o.x = fmaxf(o.x, 0.f); o.y = fmaxf(o.y, 0.f);
                o.z = fmaxf(o.z, 0.f); o.w = fmaxf(o.w, 0.f);
            } else if (EPI == 2) {
                o.x *= alpha; o.y *= alpha; o.z *= alpha; o.w *= alpha;
            }
            *(float4*)&C[(size_t)grow * N + gcol] = o;
        }
    }
}

// ---------------------------------------------------------------------------
// Vector reduction (no return) to global: 4 channels in one instruction
// ---------------------------------------------------------------------------
__device__ __forceinline__ void red_add_v4(float* p, float4 v)
{
    asm volatile("red.global.add.v4.f32 [%0], {%1, %2, %3, %4};"
                 :: "l"(p), "f"(v.x), "f"(v.y), "f"(v.z), "f"(v.w)
                 : "memory");
}

// ---------------------------------------------------------------------------
// Edge kernel: one warp per edge (grid-stride).
//   - gather emb2 rows, sum, relu                 (edge2)
//   - gather emb1 rows, leave-one-out prod, tanh  (term[4][64] in SMEM)
//   - GEMV: term @ Wq  (Wq staged in SMEM)
//   - scatter-add contrib per member via red.v4
// Lane l owns output channels [4l, 4l+4).
// ---------------------------------------------------------------------------
__global__ __launch_bounds__(256) void edge_kernel(
    const int*   __restrict__ edges,
    const float* __restrict__ emb1,
    const float* __restrict__ emb2,
    const float4* __restrict__ Wq4,     // [RANK][OUTD/4]
    const float* __restrict__ bq,
    float* __restrict__ out)
{
    __shared__ float4 Wq_s[RANK * (OUTD / 4)];  // 32 KB
    __shared__ float4 term_s[8][RANK];          // per-warp: term[r] = (k0..k3), 8 KB
    __shared__ float  bq_s[OUTD];

    const int tid  = threadIdx.x;
    const int warp = tid >> 5;
    const int lane = tid & 31;

    for (int i = tid; i < RANK * (OUTD / 4); i += 256) Wq_s[i] = Wq4[i];
    for (int i = tid; i < OUTD; i += 256) bq_s[i] = bq[i];
    __syncthreads();

    const float4 bqv = *(const float4*)&bq_s[lane * 4];

    const int stride = gridDim.x * 8;
    for (int e = blockIdx.x * 8 + warp; e < E_EDGES; e += stride) {
        const int4 idx = *(const int4*)&edges[e * 4];

        // edge2 = relu(sum_k emb2[idx_k])  -- lane's 4 channels
        float4 a0 = *(const float4*)&emb2[(size_t)idx.x * OUTD + lane * 4];
        float4 a1 = *(const float4*)&emb2[(size_t)idx.y * OUTD + lane * 4];
        float4 a2 = *(const float4*)&emb2[(size_t)idx.z * OUTD + lane * 4];
        float4 a3 = *(const float4*)&emb2[(size_t)idx.w * OUTD + lane * 4];
        float4 s2;
        s2.x = fmaxf(a0.x + a1.x + a2.x + a3.x, 0.f);
        s2.y = fmaxf(a0.y + a1.y + a2.y + a3.y, 0.f);
        s2.z = fmaxf(a0.z + a1.z + a2.z + a3.z, 0.f);
        s2.w = fmaxf(a0.w + a1.w + a2.w + a3.w, 0.f);

        // term[k][r] = tanh(C1 * prod_{j!=k} g_j[r]); 2 r-values per lane
#pragma unroll
        for (int rr = 0; rr < 2; rr++) {
            const int r = lane + rr * 32;
            const float g0 = emb1[(size_t)idx.x * RANK + r];
            const float g1 = emb1[(size_t)idx.y * RANK + r];
            const float g2 = emb1[(size_t)idx.z * RANK + r];
            const float g3 = emb1[(size_t)idx.w * RANK + r];
            const float a01 = g0 * g1, a23 = g2 * g3;
            float4 t;
            t.x = tanhf(C1V * (g1 * a23));
            t.y = tanhf(C1V * (g0 * a23));
            t.z = tanhf(C1V * (a01 * g3));
            t.w = tanhf(C1V * (a01 * g2));
            term_s[warp][r] = t;
        }
        __syncwarp();

        // GEMV: acc_k[c] = sum_r term[k][r] * Wq[r][c], lane's 4 channels
        float4 acc0 = make_float4(0.f, 0.f, 0.f, 0.f);
        float4 acc1 = acc0, acc2 = acc0, acc3 = acc0;
#pragma unroll
        for (int r = 0; r < RANK; r++) {
            const float4 t = term_s[warp][r];   // broadcast
            const float4 w = Wq_s[r * (OUTD / 4) + lane];
            acc0.x += t.x * w.x; acc0.y += t.x * w.y; acc0.z += t.x * w.z; acc0.w += t.x * w.w;
            acc1.x += t.y * w.x; acc1.y += t.y * w.y; acc1.z += t.y * w.z; acc1.w += t.y * w.w;
            acc2.x += t.z * w.x; acc2.y += t.z * w.y; acc2.z += t.z * w.z; acc2.w += t.z * w.w;
            acc3.x += t.w * w.x; acc3.y += t.w * w.y; acc3.z += t.w * w.z; acc3.w += t.w * w.w;
        }

        float4 base;
        base.x = bqv.x + s2.x; base.y = bqv.y + s2.y;
        base.z = bqv.z + s2.z; base.w = bqv.w + s2.w;

        float4 v;
        v.x = acc0.x + base.x; v.y = acc0.y + base.y; v.z = acc0.z + base.z; v.w = acc0.w + base.w;
        red_add_v4(&out[(size_t)idx.x * OUTD + lane * 4], v);
        v.x = acc1.x + base.x; v.y = acc1.y + base.y; v.z = acc1.z + base.z; v.w = acc1.w + base.w;
        red_add_v4(&out[(size_t)idx.y * OUTD + lane * 4], v);
        v.x = acc2.x + base.x; v.y = acc2.y + base.y; v.z = acc2.z + base.z; v.w = acc2.w + base.w;
        red_add_v4(&out[(size_t)idx.z * OUTD + lane * 4], v);
        v.x = acc3.x + base.x; v.y = acc3.y + base.y; v.z = acc3.z + base.z; v.w = acc3.w + base.w;
        red_add_v4(&out[(size_t)idx.w * OUTD + lane * 4], v);

        __syncwarp();   // protect term_s before next iteration's writes
    }
}

// ---------------------------------------------------------------------------
__global__ void zero_kernel(float4* __restrict__ p, int n4)
{
    const float4 z = make_float4(0.f, 0.f, 0.f, 0.f);
    for (int i = blockIdx.x * blockDim.x + threadIdx.x; i < n4;
         i += gridDim.x * blockDim.x)
        p[i] = z;
}

__global__ void finalize_kernel(float4* __restrict__ p, int n4)
{
    for (int i = blockIdx.x * blockDim.x + threadIdx.x; i < n4;
         i += gridDim.x * blockDim.x) {
        float4 v = p[i];
        v.x = fmaxf(v.x * 0.125f, 0.f);
        v.y = fmaxf(v.y * 0.125f, 0.f);
        v.z = fmaxf(v.z * 0.125f, 0.f);
        v.w = fmaxf(v.w * 0.125f, 0.f);
        p[i] = v;
    }
}

// ---------------------------------------------------------------------------
extern "C" void kernel_launch(void* const* d_in, const int* in_sizes, int n_in,
                              void* d_out, int out_size)
{
    const float* emb   = (const float*)d_in[0];
    const float* Wp    = (const float*)d_in[1];
    const float* bp    = (const float*)d_in[2];
    const float* Wq    = (const float*)d_in[3];
    const float* bq    = (const float*)d_in[4];
    const float* W1    = (const float*)d_in[5];
    const float* b1    = (const float*)d_in[6];
    const float* W2    = (const float*)d_in[7];
    const float* b2    = (const float*)d_in[8];
    const int*   edges = (const int*)d_in[9];
    float* out = (float*)d_out;

    float *p_emb1, *p_h, *p_emb2;
    cudaGetSymbolAddress((void**)&p_emb1, g_emb1);
    cudaGetSymbolAddress((void**)&p_h,    g_h);
    cudaGetSymbolAddress((void**)&p_emb2, g_emb2);

    const int n4 = out_size / 4;  // N*OUTD/4 float4s

    // 1) zero the accumulator (d_out)
    zero_kernel<<<2048, 256>>>((float4*)out, n4);

    const int grid_m = (N_NODES + 127) / 128;  // 782

    // 2) emb1_scaled = num * (emb @ Wp + bp)        [1e5, 64]
    sgemm_kernel<128, 64, 16, 8, 4, 2><<<dim3(1, grid_m), 256>>>(
        N_NODES, RANK, FEAT, emb, Wp, bp, p_emb1, NUMV);

    // 3) h = relu(emb @ W1 + b1)                    [1e5, 512]
    sgemm_kernel<128, 128, 16, 8, 8, 1><<<dim3(HID / 128, grid_m), 256>>>(
        N_NODES, HID, FEAT, emb, W1, b1, p_h, 1.0f);

    // 4) emb2 = h @ W2 + b2                         [1e5, 128]
    sgemm_kernel<128, 128, 16, 8, 8, 0><<<dim3(1, grid_m), 256>>>(
        N_NODES, OUTD, HID, p_h, W2, b2, p_emb2, 1.0f);

    // 5) edge stage: gather, exclusive-prod, tanh, GEMV, scatter-add
    edge_kernel<<<740, 256>>>(edges, p_emb1, p_emb2,
                              (const float4*)Wq, bq, out);

    // 6) out = relu(out / DEG)
    finalize_kernel<<<2048, 256>>>((float4*)out, n4);
}

// round 9
// speedup vs baseline: 1.0010x; 1.0010x over previous
#include <cuda_runtime.h>
#include <math.h>
#include <stdint.h>

// Problem constants (fixed by the dataset)
#define N_NODES 100000
#define FEAT    256
#define RANK    64
#define HID     512
#define OUTD    128
#define E_EDGES 200000
#define KORD    4
#define DEG     8

// num = DEG^(1/K) = 8^0.25
#define NUMV 1.6817928305074290860f
// C1 = num / (K-1)! = num / 6
#define C1V  (NUMV / 6.0f)

// -------- scratch (device globals: the sanctioned no-alloc workaround) -----
__device__ float g_emb1[(size_t)N_NODES * RANK];   // num*(emb@Wp + bp)   25.6 MB
__device__ float g_h   [(size_t)N_NODES * HID];    // relu(emb@W1 + b1)  204.8 MB
__device__ float g_emb2[(size_t)N_NODES * OUTD];   // h@W2 + b2          51.2 MB

// ---------------------------------------------------------------------------
// Generic register-blocked SGEMM: C[M,N] = epi(A[M,K] @ B[K,N] + bias)
// EPI: 0 = none, 1 = relu, 2 = scale by alpha after bias
// Requires: K % BK == 0, N % BN == 0 (true for all three calls). M guarded.
// ---------------------------------------------------------------------------
template <int BM, int BN, int BK, int TM, int TN, int EPI>
__global__ __launch_bounds__(256) void sgemm_kernel(
    int M, int N, int K,
    const float* __restrict__ A, const float* __restrict__ B,
    const float* __restrict__ bias, float* __restrict__ C, float alpha)
{
    static_assert((BM / TM) * (BN / TN) == 256, "256 threads");
    __shared__ float As[BK][BM];   // A tile stored transposed
    __shared__ float Bs[BK][BN];

    const int tid     = threadIdx.x;
    const int tcols   = BN / TN;
    const int tr      = tid / tcols;
    const int tc      = tid % tcols;
    const int rowBase = blockIdx.y * BM;
    const int colBase = blockIdx.x * BN;

    const int aRow0 = tid / (BK / 4);
    const int aCol  = (tid % (BK / 4)) * 4;
    constexpr int ASTRIDE = 256 / (BK / 4);
    const int bRow0 = tid / (BN / 4);
    const int bCol  = (tid % (BN / 4)) * 4;
    constexpr int BSTRIDE = 256 / (BN / 4);

    float acc[TM][TN];
#pragma unroll
    for (int i = 0; i < TM; i++)
#pragma unroll
        for (int j = 0; j < TN; j++) acc[i][j] = 0.0f;

    for (int k0 = 0; k0 < K; k0 += BK) {
        // Load A tile (transposed into SMEM), guard rows beyond M
#pragma unroll
        for (int r = 0; r < BM; r += ASTRIDE) {
            const int row  = r + aRow0;
            const int grow = rowBase + row;
            float4 v = make_float4(0.f, 0.f, 0.f, 0.f);
            if (grow < M)
                v = *(const float4*)&A[(size_t)grow * K + k0 + aCol];
            As[aCol + 0][row] = v.x;
            As[aCol + 1][row] = v.y;
            As[aCol + 2][row] = v.z;
            As[aCol + 3][row] = v.w;
        }
        // Load B tile
#pragma unroll
        for (int r = 0; r < BK; r += BSTRIDE) {
            const int row = r + bRow0;
            *(float4*)&Bs[row][bCol] =
                *(const float4*)&B[(size_t)(k0 + row) * N + colBase + bCol];
        }
        __syncthreads();

#pragma unroll
        for (int kk = 0; kk < BK; kk++) {
            float ra[TM], rb[TN];
#pragma unroll
            for (int i = 0; i < TM; i += 4)
                *(float4*)&ra[i] = *(const float4*)&As[kk][tr * TM + i];
#pragma unroll
            for (int j = 0; j < TN; j += 4)
                *(float4*)&rb[j] = *(const float4*)&Bs[kk][tc * TN + j];
#pragma unroll
            for (int i = 0; i < TM; i++)
#pragma unroll
                for (int j = 0; j < TN; j++)
                    acc[i][j] += ra[i] * rb[j];
        }
        __syncthreads();
    }

    // Epilogue
#pragma unroll
    for (int i = 0; i < TM; i++) {
        const int grow = rowBase + tr * TM + i;
        if (grow >= M) continue;
#pragma unroll
        for (int j = 0; j < TN; j += 4) {
            const int gcol = colBase + tc * TN + j;
            const float4 bv = *(const float4*)&bias[gcol];
            float4 o;
            o.x = acc[i][j + 0] + bv.x;
            o.y = acc[i][j + 1] + bv.y;
            o.z = acc[i][j + 2] + bv.z;
            o.w = acc[i][j + 3] + bv.w;
            if (EPI == 1) {
                o.x = fmaxf(o.x, 0.f); o.y = fmaxf(o.y, 0.f);
                o.z = fmaxf(o.z, 0.f); o.w = fmaxf(o.w, 0.f);
            } else if (EPI == 2) {
                o.x *= alpha; o.y *= alpha; o.z *= alpha; o.w *= alpha;
            }
            *(float4*)&C[(size_t)grow * N + gcol] = o;
        }
    }
}

// ---------------------------------------------------------------------------
// Vector reduction (no return) to global: 4 channels in one instruction
// ---------------------------------------------------------------------------
__device__ __forceinline__ void red_add_v4(float* p, float4 v)
{
    asm volatile("red.global.add.v4.f32 [%0], {%1, %2, %3, %4};"
                 :: "l"(p), "f"(v.x), "f"(v.y), "f"(v.z), "f"(v.w)
                 : "memory");
}

// ---------------------------------------------------------------------------
// Edge kernel: one warp per edge (grid-stride).
//   - gather emb2 rows, sum, relu                 (edge2)
//   - gather emb1 rows, leave-one-out prod, tanh  (term[4][64] in SMEM)
//   - GEMV: term @ Wq  (Wq staged in SMEM)
//   - scatter-add contrib per member via red.v4
// Lane l owns output channels [4l, 4l+4).
// ---------------------------------------------------------------------------
__global__ __launch_bounds__(256) void edge_kernel(
    const int*   __restrict__ edges,
    const float* __restrict__ emb1,
    const float* __restrict__ emb2,
    const float4* __restrict__ Wq4,     // [RANK][OUTD/4]
    const float* __restrict__ bq,
    float* __restrict__ out)
{
    __shared__ float4 Wq_s[RANK * (OUTD / 4)];  // 32 KB
    __shared__ float4 term_s[8][RANK];          // per-warp: term[r] = (k0..k3), 8 KB
    __shared__ float  bq_s[OUTD];

    const int tid  = threadIdx.x;
    const int warp = tid >> 5;
    const int lane = tid & 31;

    for (int i = tid; i < RANK * (OUTD / 4); i += 256) Wq_s[i] = Wq4[i];
    for (int i = tid; i < OUTD; i += 256) bq_s[i] = bq[i];
    __syncthreads();

    const float4 bqv = *(const float4*)&bq_s[lane * 4];

    const int stride = gridDim.x * 8;
    for (int e = blockIdx.x * 8 + warp; e < E_EDGES; e += stride) {
        const int4 idx = *(const int4*)&edges[e * 4];

        // edge2 = relu(sum_k emb2[idx_k])  -- lane's 4 channels
        float4 a0 = *(const float4*)&emb2[(size_t)idx.x * OUTD + lane * 4];
        float4 a1 = *(const float4*)&emb2[(size_t)idx.y * OUTD + lane * 4];
        float4 a2 = *(const float4*)&emb2[(size_t)idx.z * OUTD + lane * 4];
        float4 a3 = *(const float4*)&emb2[(size_t)idx.w * OUTD + lane * 4];
        float4 s2;
        s2.x = fmaxf(a0.x + a1.x + a2.x + a3.x, 0.f);
        s2.y = fmaxf(a0.y + a1.y + a2.y + a3.y, 0.f);
        s2.z = fmaxf(a0.z + a1.z + a2.z + a3.z, 0.f);
        s2.w = fmaxf(a0.w + a1.w + a2.w + a3.w, 0.f);

        // term[k][r] = tanh(C1 * prod_{j!=k} g_j[r]); 2 r-values per lane
#pragma unroll
        for (int rr = 0; rr < 2; rr++) {
            const int r = lane + rr * 32;
            const float g0 = emb1[(size_t)idx.x * RANK + r];
            const float g1 = emb1[(size_t)idx.y * RANK + r];
            const float g2 = emb1[(size_t)idx.z * RANK + r];
            const float g3 = emb1[(size_t)idx.w * RANK + r];
            const float a01 = g0 * g1, a23 = g2 * g3;
            float4 t;
            t.x = tanhf(C1V * (g1 * a23));
            t.y = tanhf(C1V * (g0 * a23));
            t.z = tanhf(C1V * (a01 * g3));
            t.w = tanhf(C1V * (a01 * g2));
            term_s[warp][r] = t;
        }
        __syncwarp();

        // GEMV: acc_k[c] = sum_r term[k][r] * Wq[r][c], lane's 4 channels
        float4 acc0 = make_float4(0.f, 0.f, 0.f, 0.f);
        float4 acc1 = acc0, acc2 = acc0, acc3 = acc0;
#pragma unroll
        for (int r = 0; r < RANK; r++) {
            const float4 t = term_s[warp][r];   // broadcast
            const float4 w = Wq_s[r * (OUTD / 4) + lane];
            acc0.x += t.x * w.x; acc0.y += t.x * w.y; acc0.z += t.x * w.z; acc0.w += t.x * w.w;
            acc1.x += t.y * w.x; acc1.y += t.y * w.y; acc1.z += t.y * w.z; acc1.w += t.y * w.w;
            acc2.x += t.z * w.x; acc2.y += t.z * w.y; acc2.z += t.z * w.z; acc2.w += t.z * w.w;
            acc3.x += t.w * w.x; acc3.y += t.w * w.y; acc3.z += t.w * w.z; acc3.w += t.w * w.w;
        }

        float4 base;
        base.x = bqv.x + s2.x; base.y = bqv.y + s2.y;
        base.z = bqv.z + s2.z; base.w = bqv.w + s2.w;

        float4 v;
        v.x = acc0.x + base.x; v.y = acc0.y + base.y; v.z = acc0.z + base.z; v.w = acc0.w + base.w;
        red_add_v4(&out[(size_t)idx.x * OUTD + lane * 4], v);
        v.x = acc1.x + base.x; v.y = acc1.y + base.y; v.z = acc1.z + base.z; v.w = acc1.w + base.w;
        red_add_v4(&out[(size_t)idx.y * OUTD + lane * 4], v);
        v.x = acc2.x + base.x; v.y = acc2.y + base.y; v.z = acc2.z + base.z; v.w = acc2.w + base.w;
        red_add_v4(&out[(size_t)idx.z * OUTD + lane * 4], v);
        v.x = acc3.x + base.x; v.y = acc3.y + base.y; v.z = acc3.z + base.z; v.w = acc3.w + base.w;
        red_add_v4(&out[(size_t)idx.w * OUTD + lane * 4], v);

        __syncwarp();   // protect term_s before next iteration's writes
    }
}

// ---------------------------------------------------------------------------
__global__ void zero_kernel(float4* __restrict__ p, int n4)
{
    const float4 z = make_float4(0.f, 0.f, 0.f, 0.f);
    for (int i = blockIdx.x * blockDim.x + threadIdx.x; i < n4;
         i += gridDim.x * blockDim.x)
        p[i] = z;
}

__global__ void finalize_kernel(float4* __restrict__ p, int n4)
{
    for (int i = blockIdx.x * blockDim.x + threadIdx.x; i < n4;
         i += gridDim.x * blockDim.x) {
        float4 v = p[i];
        v.x = fmaxf(v.x * 0.125f, 0.f);
        v.y = fmaxf(v.y * 0.125f, 0.f);
        v.z = fmaxf(v.z * 0.125f, 0.f);
        v.w = fmaxf(v.w * 0.125f, 0.f);
        p[i] = v;
    }
}

// ---------------------------------------------------------------------------
extern "C" void kernel_launch(void* const* d_in, const int* in_sizes, int n_in,
                              void* d_out, int out_size)
{
    const float* emb   = (const float*)d_in[0];
    const float* Wp    = (const float*)d_in[1];
    const float* bp    = (const float*)d_in[2];
    const float* Wq    = (const float*)d_in[3];
    const float* bq    = (const float*)d_in[4];
    const float* W1    = (const float*)d_in[5];
    const float* b1    = (const float*)d_in[6];
    const float* W2    = (const float*)d_in[7];
    const float* b2    = (const float*)d_in[8];
    const int*   edges = (const int*)d_in[9];
    float* out = (float*)d_out;

    float *p_emb1, *p_h, *p_emb2;
    cudaGetSymbolAddress((void**)&p_emb1, g_emb1);
    cudaGetSymbolAddress((void**)&p_h,    g_h);
    cudaGetSymbolAddress((void**)&p_emb2, g_emb2);

    const int n4 = out_size / 4;  // N*OUTD/4 float4s

    // 1) zero the accumulator (d_out)
    zero_kernel<<<2048, 256>>>((float4*)out, n4);

    const int grid_m = (N_NODES + 127) / 128;  // 782

    // 2) emb1_scaled = num * (emb @ Wp + bp)        [1e5, 64]
    sgemm_kernel<128, 64, 16, 8, 4, 2><<<dim3(1, grid_m), 256>>>(
        N_NODES, RANK, FEAT, emb, Wp, bp, p_emb1, NUMV);

    // 3) h = relu(emb @ W1 + b1)                    [1e5, 512]
    sgemm_kernel<128, 128, 16, 8, 8, 1><<<dim3(HID / 128, grid_m), 256>>>(
        N_NODES, HID, FEAT, emb, W1, b1, p_h, 1.0f);

    // 4) emb2 = h @ W2 + b2                         [1e5, 128]
    sgemm_kernel<128, 128, 16, 8, 8, 0><<<dim3(1, grid_m), 256>>>(
        N_NODES, OUTD, HID, p_h, W2, b2, p_emb2, 1.0f);

    // 5) edge stage: gather, exclusive-prod, tanh, GEMV, scatter-add
    edge_kernel<<<740, 256>>>(edges, p_emb1, p_emb2,
                              (const float4*)Wq, bq, out);

    // 6) out = relu(out / DEG)
    finalize_kernel<<<2048, 256>>>((float4*)out, n4);
}

// round 12
// speedup vs baseline: 1.7778x; 1.7760x over previous
#include <cuda_runtime.h>
#include <math.h>
#include <stdint.h>

// Problem constants (fixed by the dataset)
#define N_NODES 100000
#define FEAT    256
#define RANK    64
#define HID     512
#define OUTD    128
#define E_EDGES 200000
#define KORD    4
#define DEG     8

// num = DEG^(1/K) = 8^0.25
#define NUMV 1.6817928305074290860f
// C1 = num / (K-1)! = num / 6
#define C1V  (NUMV / 6.0f)

// -------- scratch (device globals: the sanctioned no-alloc workaround) -----
__device__ float g_emb1[(size_t)N_NODES * RANK];   // num*(emb@Wp + bp)   25.6 MB
__device__ float g_h   [(size_t)N_NODES * HID];    // relu(emb@W1 + b1)  204.8 MB
__device__ float g_emb2[(size_t)N_NODES * OUTD];   // h@W2 + b2          51.2 MB
__device__ float g_embr[(size_t)N_NODES * FEAT];   // tf32-rounded emb  102.4 MB
__device__ float g_W1t [(size_t)HID * FEAT];       // W1^T, tf32-rounded
__device__ float g_W2t [(size_t)OUTD * HID];       // W2^T, tf32-rounded

// ---------------------------------------------------------------------------
// tf32 helpers
// ---------------------------------------------------------------------------
__device__ __forceinline__ float to_tf32_rna(float x)
{
    uint32_t u;
    asm("cvt.rna.tf32.f32 %0, %1;" : "=r"(u) : "f"(x));
    return __uint_as_float(u);
}

__device__ __forceinline__ void ldsm_x4(uint32_t* r, uint32_t addr)
{
    asm volatile("ldmatrix.sync.aligned.m8n8.x4.shared.b16 {%0,%1,%2,%3}, [%4];"
                 : "=r"(r[0]), "=r"(r[1]), "=r"(r[2]), "=r"(r[3]) : "r"(addr));
}

__device__ __forceinline__ void mma_tf32(float* c, const uint32_t* a,
                                         uint32_t b0, uint32_t b1)
{
    asm volatile(
        "mma.sync.aligned.m16n8k8.row.col.f32.tf32.tf32.f32 "
        "{%0,%1,%2,%3}, {%4,%5,%6,%7}, {%8,%9}, {%0,%1,%2,%3};"
        : "+f"(c[0]), "+f"(c[1]), "+f"(c[2]), "+f"(c[3])
        : "r"(a[0]), "r"(a[1]), "r"(a[2]), "r"(a[3]), "r"(b0), "r"(b1));
}

__device__ __forceinline__ void cpasync16(uint32_t dst, const void* src, int bytes)
{
    asm volatile("cp.async.cg.shared.global [%0], [%1], 16, %2;"
                 :: "r"(dst), "l"(src), "r"(bytes));
}

// ---------------------------------------------------------------------------
// tf32 tensor-core GEMM:  C[M,N] = epi(A[M,K] @ Bt[N,K]^T + bias)
// EPI: 0 = none, 1 = relu then round-to-tf32 (feeds next tf32 GEMM)
// A, Bt assumed tf32-prerounded. Requires N%128==0, K%32==0. M guarded.
// Block: 256 threads = 8 warps (4 m x 2 n); BM=128, BN=128, BK=32.
// SMEM tiles k-major with XOR quad swizzle; ldmatrix for both operands.
// ---------------------------------------------------------------------------
template <int EPI>
__global__ __launch_bounds__(256) void tf32_gemm_kernel(
    int M, int N, int K,
    const float* __restrict__ A,
    const float* __restrict__ Bt,
    const float* __restrict__ bias,
    float* __restrict__ C)
{
    extern __shared__ float smem[];
    float* As = smem;                 // 2 x 128 x 32
    float* Bs = smem + 2 * 128 * 32;  // 2 x 128 x 32

    const int tid  = threadIdx.x;
    const int warp = tid >> 5;
    const int lane = tid & 31;
    const int wm0  = (warp & 3) * 32;
    const int wn0  = (warp >> 2) * 64;
    const int rowBase = blockIdx.y * 128;
    const int colBase = blockIdx.x * 128;

    const uint32_t as_u32 = (uint32_t)__cvta_generic_to_shared(As);
    const uint32_t bs_u32 = (uint32_t)__cvta_generic_to_shared(Bs);

    // loader map: 4 float4 per thread per operand tile
    int ldR[4], ldQ[4];
#pragma unroll
    for (int i = 0; i < 4; i++) {
        int lin = i * 256 + tid;
        ldR[i] = lin >> 3;
        ldQ[i] = lin & 7;
    }

    const int nt = K / 32;

    // per-lane fragment address constants
    int mrow[2], mswz[2];
#pragma unroll
    for (int f = 0; f < 2; f++) {
        mrow[f] = wm0 + f * 16 + (lane & 15);
        mswz[f] = mrow[f] & 7;
    }
    const int kqaH = lane >> 4;          // A k-quad half select
    int nrow[4], nswz[4];
#pragma unroll
    for (int p = 0; p < 4; p++) {
        nrow[p] = wn0 + p * 16 + (lane & 7) + ((lane >> 4) << 3);
        nswz[p] = nrow[p] & 7;
    }
    const int kqbH = (lane >> 3) & 1;    // B k-quad half select

    float acc[2][8][4];
#pragma unroll
    for (int f = 0; f < 2; f++)
#pragma unroll
        for (int j = 0; j < 8; j++)
#pragma unroll
            for (int v = 0; v < 4; v++) acc[f][j][v] = 0.0f;

    auto issue_tile = [&](int kt, int buf) {
        const uint32_t aBase = as_u32 + buf * (128 * 32 * 4);
        const uint32_t bBase = bs_u32 + buf * (128 * 32 * 4);
#pragma unroll
        for (int i = 0; i < 4; i++) {
            const int r = ldR[i], q = ldQ[i];
            const int so = (r * 32 + 4 * (q ^ (r & 7))) * 4;
            // A (row-guarded, zero-fill OOB)
            const int grow = rowBase + r;
            cpasync16(aBase + so,
                      A + (size_t)grow * K + kt * 32 + q * 4,
                      grow < M ? 16 : 0);
            // Bt (always in range: N,K aligned)
            cpasync16(bBase + so,
                      Bt + (size_t)(colBase + r) * K + kt * 32 + q * 4, 16);
        }
        asm volatile("cp.async.commit_group;");
    };

    issue_tile(0, 0);

    for (int kt = 0; kt < nt; kt++) {
        const int buf = kt & 1;
        if (kt + 1 < nt) {
            issue_tile(kt + 1, buf ^ 1);
            asm volatile("cp.async.wait_group 1;");
        } else {
            asm volatile("cp.async.wait_group 0;");
        }
        __syncthreads();

        const uint32_t aB = as_u32 + buf * (128 * 32 * 4);
        const uint32_t bB = bs_u32 + buf * (128 * 32 * 4);

#pragma unroll
        for (int ks = 0; ks < 4; ks++) {
            uint32_t ra[2][4], rb[4][4];
#pragma unroll
            for (int f = 0; f < 2; f++) {
                const int kq = 2 * ks + kqaH;
                ldsm_x4(ra[f], aB + (mrow[f] * 32 + 4 * (kq ^ mswz[f])) * 4);
            }
#pragma unroll
            for (int p = 0; p < 4; p++) {
                const int kq = 2 * ks + kqbH;
                ldsm_x4(rb[p], bB + (nrow[p] * 32 + 4 * (kq ^ nswz[p])) * 4);
            }
#pragma unroll
            for (int f = 0; f < 2; f++)
#pragma unroll
                for (int j = 0; j < 8; j++)
                    mma_tf32(acc[f][j], ra[f],
                             rb[j >> 1][(j & 1) * 2],
                             rb[j >> 1][(j & 1) * 2 + 1]);
        }
        __syncthreads();
    }

    // Epilogue: C frag (m16n8): c0,c1 at (lane/4, 2*(lane%4)+{0,1}); c2,c3 at row+8
#pragma unroll
    for (int f = 0; f < 2; f++) {
        const int gm0 = rowBase + wm0 + f * 16 + (lane >> 2);
#pragma unroll
        for (int j = 0; j < 8; j++) {
            const int gn = colBase + wn0 + j * 8 + (lane & 3) * 2;
            const float2 bv = *(const float2*)&bias[gn];
            float v0 = acc[f][j][0] + bv.x;
            float v1 = acc[f][j][1] + bv.y;
            float v2 = acc[f][j][2] + bv.x;
            float v3 = acc[f][j][3] + bv.y;
            if (EPI == 1) {
                v0 = to_tf32_rna(fmaxf(v0, 0.f));
                v1 = to_tf32_rna(fmaxf(v1, 0.f));
                v2 = to_tf32_rna(fmaxf(v2, 0.f));
                v3 = to_tf32_rna(fmaxf(v3, 0.f));
            }
            if (gm0 < M)
                *(float2*)&C[(size_t)gm0 * N + gn] = make_float2(v0, v1);
            if (gm0 + 8 < M)
                *(float2*)&C[(size_t)(gm0 + 8) * N + gn] = make_float2(v2, v3);
        }
    }
}

// ---------------------------------------------------------------------------
// Prologue kernels: tf32 rounding + weight transpose(+round)
// ---------------------------------------------------------------------------
__global__ void round_kernel(const float4* __restrict__ in,
                             float4* __restrict__ out, int n4)
{
    for (int i = blockIdx.x * blockDim.x + threadIdx.x; i < n4;
         i += gridDim.x * blockDim.x) {
        float4 v = in[i];
        v.x = to_tf32_rna(v.x); v.y = to_tf32_rna(v.y);
        v.z = to_tf32_rna(v.z); v.w = to_tf32_rna(v.w);
        out[i] = v;
    }
}

__global__ void transpose_round_kernel(const float* __restrict__ src,
                                       float* __restrict__ dst, int R, int C)
{
    __shared__ float t[32][33];
    const int c0 = blockIdx.x * 32, r0 = blockIdx.y * 32;
    const int x = threadIdx.x, y = threadIdx.y;   // 32 x 8
#pragma unroll
    for (int i = 0; i < 32; i += 8)
        t[y + i][x] = src[(size_t)(r0 + y + i) * C + c0 + x];
    __syncthreads();
#pragma unroll
    for (int i = 0; i < 32; i += 8)
        dst[(size_t)(c0 + y + i) * R + r0 + x] = to_tf32_rna(t[x][y + i]);
}

// ---------------------------------------------------------------------------
// fp32 register-blocked SGEMM (kept for the precision-critical Wp path)
// EPI: 0 = none, 1 = relu, 2 = scale by alpha after bias
// ---------------------------------------------------------------------------
template <int BM, int BN, int BK, int TM, int TN, int EPI>
__global__ __launch_bounds__(256) void sgemm_kernel(
    int M, int N, int K,
    const float* __restrict__ A, const float* __restrict__ B,
    const float* __restrict__ bias, float* __restrict__ C, float alpha)
{
    static_assert((BM / TM) * (BN / TN) == 256, "256 threads");
    __shared__ float As[BK][BM];
    __shared__ float Bs[BK][BN];

    const int tid     = threadIdx.x;
    const int tcols   = BN / TN;
    const int tr      = tid / tcols;
    const int tc      = tid % tcols;
    const int rowBase = blockIdx.y * BM;
    const int colBase = blockIdx.x * BN;

    const int aRow0 = tid / (BK / 4);
    const int aCol  = (tid % (BK / 4)) * 4;
    constexpr int ASTRIDE = 256 / (BK / 4);
    const int bRow0 = tid / (BN / 4);
    const int bCol  = (tid % (BN / 4)) * 4;
    constexpr int BSTRIDE = 256 / (BN / 4);

    float acc[TM][TN];
#pragma unroll
    for (int i = 0; i < TM; i++)
#pragma unroll
        for (int j = 0; j < TN; j++) acc[i][j] = 0.0f;

    for (int k0 = 0; k0 < K; k0 += BK) {
#pragma unroll
        for (int r = 0; r < BM; r += ASTRIDE) {
            const int row  = r + aRow0;
            const int grow = rowBase + row;
            float4 v = make_float4(0.f, 0.f, 0.f, 0.f);
            if (grow < M)
                v = *(const float4*)&A[(size_t)grow * K + k0 + aCol];
            As[aCol + 0][row] = v.x;
            As[aCol + 1][row] = v.y;
            As[aCol + 2][row] = v.z;
            As[aCol + 3][row] = v.w;
        }
#pragma unroll
        for (int r = 0; r < BK; r += BSTRIDE) {
            const int row = r + bRow0;
            *(float4*)&Bs[row][bCol] =
                *(const float4*)&B[(size_t)(k0 + row) * N + colBase + bCol];
        }
        __syncthreads();

#pragma unroll
        for (int kk = 0; kk < BK; kk++) {
            float ra[TM], rb[TN];
#pragma unroll
            for (int i = 0; i < TM; i += 4)
                *(float4*)&ra[i] = *(const float4*)&As[kk][tr * TM + i];
#pragma unroll
            for (int j = 0; j < TN; j += 4)
                *(float4*)&rb[j] = *(const float4*)&Bs[kk][tc * TN + j];
#pragma unroll
            for (int i = 0; i < TM; i++)
#pragma unroll
                for (int j = 0; j < TN; j++)
                    acc[i][j] += ra[i] * rb[j];
        }
        __syncthreads();
    }

#pragma unroll
    for (int i = 0; i < TM; i++) {
        const int grow = rowBase + tr * TM + i;
        if (grow >= M) continue;
#pragma unroll
        for (int j = 0; j < TN; j += 4) {
            const int gcol = colBase + tc * TN + j;
            const float4 bv = *(const float4*)&bias[gcol];
            float4 o;
            o.x = acc[i][j + 0] + bv.x;
            o.y = acc[i][j + 1] + bv.y;
            o.z = acc[i][j + 2] + bv.z;
            o.w = acc[i][j + 3] + bv.w;
            if (EPI == 1) {
                o.x = fmaxf(o.x, 0.f); o.y = fmaxf(o.y, 0.f);
                o.z = fmaxf(o.z, 0.f); o.w = fmaxf(o.w, 0.f);
            } else if (EPI == 2) {
                o.x *= alpha; o.y *= alpha; o.z *= alpha; o.w *= alpha;
            }
            *(float4*)&C[(size_t)grow * N + gcol] = o;
        }
    }
}

// ---------------------------------------------------------------------------
__device__ __forceinline__ void red_add_v4(float* p, float4 v)
{
    asm volatile("red.global.add.v4.f32 [%0], {%1, %2, %3, %4};"
                 :: "l"(p), "f"(v.x), "f"(v.y), "f"(v.z), "f"(v.w)
                 : "memory");
}

// ---------------------------------------------------------------------------
// Edge kernel: one warp per edge (grid-stride). Unchanged from R8.
// ---------------------------------------------------------------------------
__global__ __launch_bounds__(256) void edge_kernel(
    const int*   __restrict__ edges,
    const float* __restrict__ emb1,
    const float* __restrict__ emb2,
    const float4* __restrict__ Wq4,
    const float* __restrict__ bq,
    float* __restrict__ out)
{
    __shared__ float4 Wq_s[RANK * (OUTD / 4)];
    __shared__ float4 term_s[8][RANK];
    __shared__ float  bq_s[OUTD];

    const int tid  = threadIdx.x;
    const int warp = tid >> 5;
    const int lane = tid & 31;

    for (int i = tid; i < RANK * (OUTD / 4); i += 256) Wq_s[i] = Wq4[i];
    for (int i = tid; i < OUTD; i += 256) bq_s[i] = bq[i];
    __syncthreads();

    const float4 bqv = *(const float4*)&bq_s[lane * 4];

    const int stride = gridDim.x * 8;
    for (int e = blockIdx.x * 8 + warp; e < E_EDGES; e += stride) {
        const int4 idx = *(const int4*)&edges[e * 4];

        float4 a0 = *(const float4*)&emb2[(size_t)idx.x * OUTD + lane * 4];
        float4 a1 = *(const float4*)&emb2[(size_t)idx.y * OUTD + lane * 4];
        float4 a2 = *(const float4*)&emb2[(size_t)idx.z * OUTD + lane * 4];
        float4 a3 = *(const float4*)&emb2[(size_t)idx.w * OUTD + lane * 4];
        float4 s2;
        s2.x = fmaxf(a0.x + a1.x + a2.x + a3.x, 0.f);
        s2.y = fmaxf(a0.y + a1.y + a2.y + a3.y, 0.f);
        s2.z = fmaxf(a0.z + a1.z + a2.z + a3.z, 0.f);
        s2.w = fmaxf(a0.w + a1.w + a2.w + a3.w, 0.f);

#pragma unroll
        for (int rr = 0; rr < 2; rr++) {
            const int r = lane + rr * 32;
            const float g0 = emb1[(size_t)idx.x * RANK + r];
            const float g1 = emb1[(size_t)idx.y * RANK + r];
            const float g2 = emb1[(size_t)idx.z * RANK + r];
            const float g3 = emb1[(size_t)idx.w * RANK + r];
            const float a01 = g0 * g1, a23 = g2 * g3;
            float4 t;
            t.x = tanhf(C1V * (g1 * a23));
            t.y = tanhf(C1V * (g0 * a23));
            t.z = tanhf(C1V * (a01 * g3));
            t.w = tanhf(C1V * (a01 * g2));
            term_s[warp][r] = t;
        }
        __syncwarp();

        float4 acc0 = make_float4(0.f, 0.f, 0.f, 0.f);
        float4 acc1 = acc0, acc2 = acc0, acc3 = acc0;
#pragma unroll
        for (int r = 0; r < RANK; r++) {
            const float4 t = term_s[warp][r];
            const float4 w = Wq_s[r * (OUTD / 4) + lane];
            acc0.x += t.x * w.x; acc0.y += t.x * w.y; acc0.z += t.x * w.z; acc0.w += t.x * w.w;
            acc1.x += t.y * w.x; acc1.y += t.y * w.y; acc1.z += t.y * w.z; acc1.w += t.y * w.w;
            acc2.x += t.z * w.x; acc2.y += t.z * w.y; acc2.z += t.z * w.z; acc2.w += t.z * w.w;
            acc3.x += t.w * w.x; acc3.y += t.w * w.y; acc3.z += t.w * w.z; acc3.w += t.w * w.w;
        }

        float4 base;
        base.x = bqv.x + s2.x; base.y = bqv.y + s2.y;
        base.z = bqv.z + s2.z; base.w = bqv.w + s2.w;

        float4 v;
        v.x = acc0.x + base.x; v.y = acc0.y + base.y; v.z = acc0.z + base.z; v.w = acc0.w + base.w;
        red_add_v4(&out[(size_t)idx.x * OUTD + lane * 4], v);
        v.x = acc1.x + base.x; v.y = acc1.y + base.y; v.z = acc1.z + base.z; v.w = acc1.w + base.w;
        red_add_v4(&out[(size_t)idx.y * OUTD + lane * 4], v);
        v.x = acc2.x + base.x; v.y = acc2.y + base.y; v.z = acc2.z + base.z; v.w = acc2.w + base.w;
        red_add_v4(&out[(size_t)idx.z * OUTD + lane * 4], v);
        v.x = acc3.x + base.x; v.y = acc3.y + base.y; v.z = acc3.z + base.z; v.w = acc3.w + base.w;
        red_add_v4(&out[(size_t)idx.w * OUTD + lane * 4], v);

        __syncwarp();
    }
}

// ---------------------------------------------------------------------------
__global__ void zero_kernel(float4* __restrict__ p, int n4)
{
    const float4 z = make_float4(0.f, 0.f, 0.f, 0.f);
    for (int i = blockIdx.x * blockDim.x + threadIdx.x; i < n4;
         i += gridDim.x * blockDim.x)
        p[i] = z;
}

__global__ void finalize_kernel(float4* __restrict__ p, int n4)
{
    for (int i = blockIdx.x * blockDim.x + threadIdx.x; i < n4;
         i += gridDim.x * blockDim.x) {
        float4 v = p[i];
        v.x = fmaxf(v.x * 0.125f, 0.f);
        v.y = fmaxf(v.y * 0.125f, 0.f);
        v.z = fmaxf(v.z * 0.125f, 0.f);
        v.w = fmaxf(v.w * 0.125f, 0.f);
        p[i] = v;
    }
}

// ---------------------------------------------------------------------------
extern "C" void kernel_launch(void* const* d_in, const int* in_sizes, int n_in,
                              void* d_out, int out_size)
{
    const float* emb   = (const float*)d_in[0];
    const float* Wp    = (const float*)d_in[1];
    const float* bp    = (const float*)d_in[2];
    const float* Wq    = (const float*)d_in[3];
    const float* bq    = (const float*)d_in[4];
    const float* W1    = (const float*)d_in[5];
    const float* b1    = (const float*)d_in[6];
    const float* W2    = (const float*)d_in[7];
    const float* b2    = (const float*)d_in[8];
    const int*   edges = (const int*)d_in[9];
    float* out = (float*)d_out;

    float *p_emb1, *p_h, *p_emb2, *p_embr, *p_W1t, *p_W2t;
    cudaGetSymbolAddress((void**)&p_emb1, g_emb1);
    cudaGetSymbolAddress((void**)&p_h,    g_h);
    cudaGetSymbolAddress((void**)&p_emb2, g_emb2);
    cudaGetSymbolAddress((void**)&p_embr, g_embr);
    cudaGetSymbolAddress((void**)&p_W1t,  g_W1t);
    cudaGetSymbolAddress((void**)&p_W2t,  g_W2t);

    const int smem_gemm = 2 * (128 * 32 + 128 * 32) * (int)sizeof(float); // 64 KB
    cudaFuncSetAttribute(tf32_gemm_kernel<0>,
                         cudaFuncAttributeMaxDynamicSharedMemorySize, smem_gemm);
    cudaFuncSetAttribute(tf32_gemm_kernel<1>,
                         cudaFuncAttributeMaxDynamicSharedMemorySize, smem_gemm);

    const int n4 = out_size / 4;

    // 0) prologue: tf32-round emb; transpose+round W1, W2
    round_kernel<<<2048, 256>>>((const float4*)emb, (float4*)p_embr,
                                N_NODES * FEAT / 4);
    transpose_round_kernel<<<dim3(HID / 32, FEAT / 32), dim3(32, 8)>>>(
        W1, p_W1t, FEAT, HID);
    transpose_round_kernel<<<dim3(OUTD / 32, HID / 32), dim3(32, 8)>>>(
        W2, p_W2t, HID, OUTD);

    // 1) zero the accumulator (d_out)
    zero_kernel<<<2048, 256>>>((float4*)out, n4);

    const int grid_m128 = (N_NODES + 127) / 128;  // 782

    // 2) emb1_scaled = num * (emb @ Wp + bp)  -- fp32 (precision-critical path)
    sgemm_kernel<128, 64, 16, 8, 4, 2><<<dim3(1, grid_m128), 256>>>(
        N_NODES, RANK, FEAT, emb, Wp, bp, p_emb1, NUMV);

    // 3) h = tf32round(relu(emb @ W1 + b1))   -- tensor cores
    tf32_gemm_kernel<1><<<dim3(HID / 128, grid_m128), 256, smem_gemm>>>(
        N_NODES, HID, FEAT, p_embr, p_W1t, b1, p_h);

    // 4) emb2 = h @ W2 + b2                   -- tensor cores
    tf32_gemm_kernel<0><<<dim3(OUTD / 128, grid_m128), 256, smem_gemm>>>(
        N_NODES, OUTD, HID, p_h, p_W2t, b2, p_emb2);

    // 5) edge stage: gather, exclusive-prod, tanh, GEMV, scatter-add
    edge_kernel<<<740, 256>>>(edges, p_emb1, p_emb2,
                              (const float4*)Wq, bq, out);

    // 6) out = relu(out / DEG)
    finalize_kernel<<<2048, 256>>>((float4*)out, n4);
}